// round 11
// baseline (speedup 1.0000x reference)
#include <cuda_runtime.h>
#include <cuda_bf16.h>
#include <cstdint>

// ---------------------------------------------------------------------------
#define BB 65536
static constexpr float LRELU = 0.01f;
static constexpr float LOG_SQRT_2PI_C = 0.91893853320467274178f;

// ---------------------------------------------------------------------------
// Device scratch
// ---------------------------------------------------------------------------
__device__ uint16_t g_obsH[(size_t)BB * 384];
__device__ uint16_t g_obsL[(size_t)BB * 384];
__device__ uint16_t g_S1H[(size_t)BB * 1536];   // [W1|Ws1|Wg1] outputs
__device__ uint16_t g_S1L[(size_t)BB * 1536];
__device__ uint16_t g_TTH[(size_t)3 * BB * 256]; // T1|T2|T3 (z-batched out)
__device__ uint16_t g_TTL[(size_t)3 * BB * 256];
__device__ uint16_t g_HH[(size_t)BB * 2048];    // 8 heads concat on N
__device__ uint16_t g_HL[(size_t)BB * 2048];
__device__ float g_PS[(size_t)8 * BB * 40];
__device__ float g_SG[(size_t)BB * 256];
__device__ float g_bcat[2048];  // [0,1024)=b1|bs1  [1024,1792)=b2|bs2|bg2  [1792,2048)=bs3|bg3

static constexpr size_t WPOOL = 1441792;
__device__ uint16_t g_Wh[WPOOL];
__device__ uint16_t g_Wl[WPOOL];

// weight pool offsets (W2/Ws2/Wg2 adjacent; Ws3/Wg3 adjacent)
static constexpr size_t O_W1s = 0;         // 256 x 1024  ([W1|Ws1])
static constexpr size_t O_Wg1 = 262144;    // 128 x 512
static constexpr size_t O_W2  = 327680;    // 512 x 256  (x3, stride 131072)
static constexpr size_t O_Ws2 = 458752;
static constexpr size_t O_Wg2 = 589824;
static constexpr size_t O_Ws3 = 720896;    // 256 x 128  (x2, stride 32768)
static constexpr size_t O_Wg3 = 753664;
static constexpr size_t O_Wp1 = 786432;    // 256 x 2048 (heads on N)
static constexpr size_t O_Wp2 = 1310720;   // 8 x (256 x 64 pad)

// ---------------------------------------------------------------------------
// PTX helpers
// ---------------------------------------------------------------------------
__device__ __forceinline__ uint32_t smem_u32(const void* p) {
    uint32_t a;
    asm("{ .reg .u64 t; cvta.to.shared.u64 t, %1; cvt.u32.u64 %0, t; }"
        : "=r"(a) : "l"(p));
    return a;
}
__device__ __forceinline__ void cpa16(uint32_t dst, const void* src) {
    asm volatile("cp.async.cg.shared.global [%0], [%1], 16;"
                 :: "r"(dst), "l"(src) : "memory");
}
__device__ __forceinline__ void cp_commit() {
    asm volatile("cp.async.commit_group;" ::: "memory");
}
template <int N> __device__ __forceinline__ void cp_wait() {
    asm volatile("cp.async.wait_group %0;" :: "n"(N) : "memory");
}
__device__ __forceinline__ void ldsm4(uint32_t* r, uint32_t addr) {
    asm volatile("ldmatrix.sync.aligned.m8n8.x4.shared.b16 {%0,%1,%2,%3}, [%4];"
                 : "=r"(r[0]), "=r"(r[1]), "=r"(r[2]), "=r"(r[3]) : "r"(addr));
}
__device__ __forceinline__ void ldsm4t(uint32_t* r, uint32_t addr) {
    asm volatile("ldmatrix.sync.aligned.m8n8.x4.trans.shared.b16 {%0,%1,%2,%3}, [%4];"
                 : "=r"(r[0]), "=r"(r[1]), "=r"(r[2]), "=r"(r[3]) : "r"(addr));
}
__device__ __forceinline__ void mma_bf16(float* d, const uint32_t* a, const uint32_t* b) {
    asm volatile(
        "mma.sync.aligned.m16n8k16.row.col.f32.bf16.bf16.f32 "
        "{%0,%1,%2,%3}, {%4,%5,%6,%7}, {%8,%9}, {%0,%1,%2,%3};"
        : "+f"(d[0]), "+f"(d[1]), "+f"(d[2]), "+f"(d[3])
        : "r"(a[0]), "r"(a[1]), "r"(a[2]), "r"(a[3]), "r"(b[0]), "r"(b[1]));
}
__device__ __forceinline__ uint32_t pack_bf2(float a, float b) {
    __nv_bfloat162 h = __floats2bfloat162_rn(a, b);
    return *reinterpret_cast<uint32_t*>(&h);
}
__device__ __forceinline__ uint16_t bfh(float v) {
    __nv_bfloat16 h = __float2bfloat16_rn(v);
    return *reinterpret_cast<uint16_t*>(&h);
}
__device__ __forceinline__ float bff(uint16_t u) {
    __nv_bfloat16 h = *reinterpret_cast<__nv_bfloat16*>(&u);
    return __bfloat162float(h);
}

// ---------------------------------------------------------------------------
// Prep
// ---------------------------------------------------------------------------
struct WDesc { const float* src; int N, Np, ldn; size_t off; int tot; };
struct WPack { WDesc d[24]; int cnt; };

__global__ void prep_weights(WPack p) {
    for (int e = 0; e < p.cnt; e++) {
        const WDesc w = p.d[e];
        for (int i = blockIdx.x * blockDim.x + threadIdx.x; i < w.tot;
             i += gridDim.x * blockDim.x) {
            int k = i / w.Np, n = i % w.Np;
            float v = (n < w.N) ? w.src[(size_t)k * w.N + n] : 0.f;
            uint16_t h = bfh(v);
            size_t dst = w.off + (size_t)k * w.ldn + n;
            g_Wh[dst] = h;
            g_Wl[dst] = bfh(v - bff(h));
        }
    }
}

__global__ void prep_obs(const float* __restrict__ src, size_t n4) {
    size_t i = (size_t)blockIdx.x * blockDim.x + threadIdx.x;
    if (i >= n4) return;
    float4 v = ((const float4*)src)[i];
    float h0 = bff(bfh(v.x)), h1 = bff(bfh(v.y));
    float h2 = bff(bfh(v.z)), h3 = bff(bfh(v.w));
    uint32_t* dh = (uint32_t*)&g_obsH[i * 4];
    uint32_t* dl = (uint32_t*)&g_obsL[i * 4];
    dh[0] = pack_bf2(h0, h1); dh[1] = pack_bf2(h2, h3);
    dl[0] = pack_bf2(v.x - h0, v.y - h1); dl[1] = pack_bf2(v.z - h2, v.w - h3);
}

__global__ void prep_bias(const float* __restrict__ b1, const float* __restrict__ bs1,
                          const float* __restrict__ b2, const float* __restrict__ bs2,
                          const float* __restrict__ bg2,
                          const float* __restrict__ bs3, const float* __restrict__ bg3) {
    int i = blockIdx.x * blockDim.x + threadIdx.x;
    if (i < 512)       g_bcat[i] = b1[i];
    else if (i < 1024) g_bcat[i] = bs1[i - 512];
    else if (i < 1280) g_bcat[i] = b2[i - 1024];
    else if (i < 1536) g_bcat[i] = bs2[i - 1280];
    else if (i < 1792) g_bcat[i] = bg2[i - 1536];
    else if (i < 1920) g_bcat[i] = bs3[i - 1792];
    else if (i < 2048) g_bcat[i] = bg3[i - 1920];
}

// ---------------------------------------------------------------------------
// Split-bf16 GEMM, CTA tile 128 x NT, 3-stage ring, ONE barrier per chunk.
// ---------------------------------------------------------------------------
template <int NT>
__global__ void __launch_bounds__(256, 2) gemm_tc3(
    const uint16_t* __restrict__ Ah, const uint16_t* __restrict__ Al, int lda,
    const uint16_t* __restrict__ Bh, const uint16_t* __restrict__ Bl, int ldb,
    const float* __restrict__ bias, int Nreal,
    float* __restrict__ Cf, uint16_t* __restrict__ Chi, uint16_t* __restrict__ Clo,
    int ldc, int K, int act, int mode,
    size_t strideAz, size_t strideBz, size_t strideCz, int biasStride)
{
    constexpr int WN   = NT / 2;
    constexpr int NI   = WN / 8;
    constexpr int BST  = NT + 8;
    constexpr int SM_AL = 10240;
    constexpr int SM_BH = 20480;
    constexpr int SM_BL = 20480 + 32 * BST * 2;
    constexpr int STAGE = 20480 + 2 * 32 * BST * 2;

    extern __shared__ __align__(16) char smem[];
    const uint32_t sb = smem_u32(smem);

    const int t    = threadIdx.x;
    const int lane = t & 31;
    const int wid  = t >> 5;
    const int wm   = wid & 3;
    const int wn   = wid >> 2;
    const int m0   = blockIdx.y * 128;
    const int n0   = blockIdx.x * NT;
    const int z    = blockIdx.z;

    const uint16_t* Abase_h = Ah + (size_t)z * strideAz;
    const uint16_t* Abase_l = Al + (size_t)z * strideAz;
    const uint16_t* Bbase_h = Bh + (size_t)z * strideBz;
    const uint16_t* Bbase_l = Bl + (size_t)z * strideBz;
    const float*    biasp   = bias + (size_t)z * biasStride;

    const int nch = K >> 5;

    auto issue = [&](int c) {
        if (c < nch) {
            const uint32_t base = sb + (c % 3) * STAGE;
            const int k0 = c << 5;
#pragma unroll
            for (int j = 0; j < 2; j++) {
                int i = t + 256 * j;
                int ar = i >> 2, as = i & 3;
                uint32_t off = (ar * 40 + as * 8) * 2;
                const uint16_t* sh = Abase_h + (size_t)(m0 + ar) * lda + k0 + as * 8;
                const uint16_t* sl = Abase_l + (size_t)(m0 + ar) * lda + k0 + as * 8;
                cpa16(base + off, sh);
                cpa16(base + SM_AL + off, sl);
            }
#pragma unroll
            for (int j = 0; j < NT / 64; j++) {
                int i = t + 256 * j;
                int br = i / (NT / 8), bs = i % (NT / 8);
                uint32_t off = (br * BST + bs * 8) * 2;
                const uint16_t* sh = Bbase_h + (size_t)(k0 + br) * ldb + n0 + bs * 8;
                const uint16_t* sl = Bbase_l + (size_t)(k0 + br) * ldb + n0 + bs * 8;
                cpa16(base + SM_BH + off, sh);
                cpa16(base + SM_BL + off, sl);
            }
        }
        cp_commit();   // unconditional: keeps group counting uniform
    };

    float acc[2][NI][4];
#pragma unroll
    for (int i = 0; i < 2; i++)
#pragma unroll
        for (int j = 0; j < NI; j++)
#pragma unroll
            for (int q = 0; q < 4; q++) acc[i][j][q] = 0.f;

    issue(0);
    issue(1);

    for (int c = 0; c < nch; c++) {
        cp_wait<1>();          // group c complete (c+1 may be pending)
        __syncthreads();       // all warps past compute(c-1); buffer (c+2)%3 free
        issue(c + 2);          // prefetch 2 ahead

        const uint32_t base = sb + (c % 3) * STAGE;
#pragma unroll
        for (int ks = 0; ks < 32; ks += 16) {
            uint32_t Afh[2][4], Afl[2][4], Bfh[NI][2], Bfl[NI][2];
            {
                int r  = lane & 15;
                int kq = (lane >> 4) * 8;
#pragma unroll
                for (int mi = 0; mi < 2; mi++) {
                    int m = wm * 32 + mi * 16 + r;
                    uint32_t off = (m * 40 + ks + kq) * 2;
                    ldsm4(Afh[mi], base + off);
                    ldsm4(Afl[mi], base + SM_AL + off);
                }
            }
            {
                int g  = lane >> 3;
                int rr = lane & 7;
                int krow = ks + (g & 1) * 8 + rr;
                int ncol = (g >> 1) * 8;
#pragma unroll
                for (int blk = 0; blk < NI / 2; blk++) {
                    int nb = wn * WN + blk * 16 + ncol;
                    uint32_t off = (krow * BST + nb) * 2;
                    ldsm4t(&Bfh[blk * 2][0], base + SM_BH + off);
                    ldsm4t(&Bfl[blk * 2][0], base + SM_BL + off);
                }
            }
#pragma unroll
            for (int mi = 0; mi < 2; mi++)
#pragma unroll
                for (int ni = 0; ni < NI; ni++) {
                    mma_bf16(acc[mi][ni], Afh[mi], Bfh[ni]);
                    mma_bf16(acc[mi][ni], Afh[mi], Bfl[ni]);
                    mma_bf16(acc[mi][ni], Afl[mi], Bfh[ni]);
                }
        }
    }

    // ---- epilogue ----
    const int r4 = lane >> 2;
    const int c2 = (lane & 3) * 2;
#pragma unroll
    for (int mi = 0; mi < 2; mi++) {
#pragma unroll
        for (int ni = 0; ni < NI; ni++) {
            int col = n0 + wn * WN + ni * 8 + c2;
            int row = m0 + wm * 32 + mi * 16 + r4;
            if (mode == 0 && col >= Nreal) continue;
            float b0 = biasp[col], b1 = biasp[col + 1];
            float v0 = acc[mi][ni][0] + b0;
            float v1 = acc[mi][ni][1] + b1;
            float v2 = acc[mi][ni][2] + b0;
            float v3 = acc[mi][ni][3] + b1;
            if (act) {
                v0 = v0 > 0.f ? v0 : LRELU * v0;
                v1 = v1 > 0.f ? v1 : LRELU * v1;
                v2 = v2 > 0.f ? v2 : LRELU * v2;
                v3 = v3 > 0.f ? v3 : LRELU * v3;
            }
            size_t i0 = (size_t)z * strideCz + (size_t)row * ldc + col;
            size_t i1 = (size_t)z * strideCz + (size_t)(row + 8) * ldc + col;
            if (mode == 0) {
                *(float2*)&Cf[i0] = make_float2(v0, v1);
                *(float2*)&Cf[i1] = make_float2(v2, v3);
            } else {
                float h0 = bff(bfh(v0)), h1 = bff(bfh(v1));
                float h2 = bff(bfh(v2)), h3 = bff(bfh(v3));
                *(uint32_t*)&Chi[i0] = pack_bf2(h0, h1);
                *(uint32_t*)&Clo[i0] = pack_bf2(v0 - h0, v1 - h1);
                *(uint32_t*)&Chi[i1] = pack_bf2(h2, h3);
                *(uint32_t*)&Clo[i1] = pack_bf2(v2 - h2, v3 - h3);
            }
        }
    }
}

// ---------------------------------------------------------------------------
// Finalize
// ---------------------------------------------------------------------------
__global__ __launch_bounds__(256) void finalize_kernel(
    const float* __restrict__ SG, const float* __restrict__ PS,
    const float* __restrict__ actions,
    const float* __restrict__ Wgate, const float* __restrict__ bgate,
    float* __restrict__ out)
{
    __shared__ float Wg_s[8 * 256];
    const int t = threadIdx.x;
    for (int i = t; i < 2048; i += 256) {
        int k = i >> 3, p = i & 7;
        Wg_s[p * 256 + k] = Wgate[i];
    }
    __syncthreads();

    const int warp = t >> 5, lane = t & 31;
    const size_t row = (size_t)blockIdx.x * 8 + warp;

    float accp[8] = {0, 0, 0, 0, 0, 0, 0, 0};
#pragma unroll
    for (int i = 0; i < 8; i++) {
        float v = SG[row * 256 + lane + 32 * i];
        v = v > 0.f ? v : LRELU * v;
#pragma unroll
        for (int p = 0; p < 8; p++)
            accp[p] += v * Wg_s[p * 256 + lane + 32 * i];
    }
#pragma unroll
    for (int off = 16; off; off >>= 1)
#pragma unroll
        for (int p = 0; p < 8; p++)
            accp[p] += __shfl_xor_sync(0xffffffffu, accp[p], off);

    float wg[8];
#pragma unroll
    for (int p = 0; p < 8; p++)
        wg[p] = expf(accp[p] + bgate[p]);

    float lp = 0.f, ent = 0.f;
    if (lane < 20) {
        float s1 = 0.f, s2 = 0.f;
#pragma unroll
        for (int p = 0; p < 8; p++) {
            const float* psr = PS + ((size_t)p * BB + row) * 40;
            float mu = psr[lane];
            float lg = psr[20 + lane];
            float inv = wg[p] * expf(-lg);
            s1 += mu * inv;
            s2 += inv;
        }
        float a = actions[row * 20 + lane];
        float z = (a - s1 / s2) * s2;
        float logsig = -logf(s2);
        lp  = -0.5f * z * z - logsig - LOG_SQRT_2PI_C;
        ent = 0.5f + LOG_SQRT_2PI_C + logsig;
    }
#pragma unroll
    for (int off = 16; off; off >>= 1) {
        lp  += __shfl_xor_sync(0xffffffffu, lp,  off);
        ent += __shfl_xor_sync(0xffffffffu, ent, off);
    }
    if (lane == 0) {
        out[row * 2]     = lp;
        out[row * 2 + 1] = ent;
    }
}

// ---------------------------------------------------------------------------
// Launcher
// ---------------------------------------------------------------------------
static constexpr int SMEM128 = 3 * (20480 + 2 * 32 * 136 * 2);  // 113664
static constexpr int SMEM64  = 3 * (20480 + 2 * 32 * 72 * 2);   // 89088

extern "C" void kernel_launch(void* const* d_in, const int* in_sizes, int n_in,
                              void* d_out, int out_size)
{
    const float* obs     = (const float*)d_in[0];
    const float* actions = (const float*)d_in[1];
    const float* W1      = (const float*)d_in[2];
    const float* b1      = (const float*)d_in[3];
    const float* W2      = (const float*)d_in[4];
    const float* b2      = (const float*)d_in[5];
    const float* Wp1     = (const float*)d_in[6];
    const float* bp1     = (const float*)d_in[7];
    const float* Wp2     = (const float*)d_in[8];
    const float* bp2     = (const float*)d_in[9];
    const float* Ws1     = (const float*)d_in[10];
    const float* bs1     = (const float*)d_in[11];
    const float* Ws2     = (const float*)d_in[12];
    const float* bs2     = (const float*)d_in[13];
    const float* Ws3     = (const float*)d_in[14];
    const float* bs3     = (const float*)d_in[15];
    const float* Wg1     = (const float*)d_in[16];
    const float* bg1     = (const float*)d_in[17];
    const float* Wg2     = (const float*)d_in[18];
    const float* bg2     = (const float*)d_in[19];
    const float* Wg3     = (const float*)d_in[20];
    const float* bg3     = (const float*)d_in[21];
    const float* Wgate   = (const float*)d_in[22];
    const float* bgate   = (const float*)d_in[23];

    uint16_t *obsH, *obsL, *S1H, *S1L, *TTH, *TTL, *HH, *HL, *Wh, *Wl;
    float *PS, *SG, *bcat;
    cudaGetSymbolAddress((void**)&obsH, g_obsH);
    cudaGetSymbolAddress((void**)&obsL, g_obsL);
    cudaGetSymbolAddress((void**)&S1H, g_S1H);
    cudaGetSymbolAddress((void**)&S1L, g_S1L);
    cudaGetSymbolAddress((void**)&TTH, g_TTH);
    cudaGetSymbolAddress((void**)&TTL, g_TTL);
    cudaGetSymbolAddress((void**)&HH, g_HH);
    cudaGetSymbolAddress((void**)&HL, g_HL);
    cudaGetSymbolAddress((void**)&Wh, g_Wh);
    cudaGetSymbolAddress((void**)&Wl, g_Wl);
    cudaGetSymbolAddress((void**)&PS, g_PS);
    cudaGetSymbolAddress((void**)&SG, g_SG);
    cudaGetSymbolAddress((void**)&bcat, g_bcat);

    cudaFuncSetAttribute(gemm_tc3<128>, cudaFuncAttributeMaxDynamicSharedMemorySize, SMEM128);
    cudaFuncSetAttribute(gemm_tc3<64>,  cudaFuncAttributeMaxDynamicSharedMemorySize, SMEM64);

    static cudaStream_t sA = nullptr, sB = nullptr;
    static cudaEvent_t evRoot = nullptr, evL2 = nullptr, evA = nullptr, evB = nullptr;
    if (sA == nullptr) {
        cudaStreamCreateWithFlags(&sA, cudaStreamNonBlocking);
        cudaStreamCreateWithFlags(&sB, cudaStreamNonBlocking);
        cudaEventCreateWithFlags(&evRoot, cudaEventDisableTiming);
        cudaEventCreateWithFlags(&evL2, cudaEventDisableTiming);
        cudaEventCreateWithFlags(&evA, cudaEventDisableTiming);
        cudaEventCreateWithFlags(&evB, cudaEventDisableTiming);
    }

    // ---- prep ----
    WPack wp{};
    int e = 0;
    wp.d[e++] = {W1,  512, 512, 1024, O_W1s,       256 * 512};
    wp.d[e++] = {Ws1, 512, 512, 1024, O_W1s + 512, 256 * 512};
    wp.d[e++] = {Wg1, 512, 512, 512,  O_Wg1, 128 * 512};
    wp.d[e++] = {W2,  256, 256, 256,  O_W2,  512 * 256};
    wp.d[e++] = {Ws2, 256, 256, 256,  O_Ws2, 512 * 256};
    wp.d[e++] = {Wg2, 256, 256, 256,  O_Wg2, 512 * 256};
    wp.d[e++] = {Ws3, 128, 128, 128,  O_Ws3, 256 * 128};
    wp.d[e++] = {Wg3, 128, 128, 128,  O_Wg3, 256 * 128};
    for (int p = 0; p < 8; p++)
        wp.d[e++] = {Wp1 + (size_t)p * 65536, 256, 256, 2048,
                     O_Wp1 + (size_t)p * 256, 256 * 256};
    for (int p = 0; p < 8; p++)
        wp.d[e++] = {Wp2 + (size_t)p * 10240, 40, 64, 64,
                     O_Wp2 + (size_t)p * 16384, 256 * 64};
    wp.cnt = e;
    prep_weights<<<512, 256>>>(wp);
    size_t n4 = (size_t)BB * 384 / 4;
    prep_obs<<<(unsigned)((n4 + 255) / 256), 256>>>(obs, n4);
    prep_bias<<<8, 256>>>(b1, bs1, b2, bs2, bg2, bs3, bg3);

    dim3 blk(256);

    // fork
    cudaEventRecord(evRoot, 0);
    cudaStreamWaitEvent(sB, evRoot, 0);

    // sB: Wg1 (independent of L1a, both read obs)
    gemm_tc3<128><<<dim3(4, 512), blk, SMEM128, sB>>>(obsH + 256, obsL + 256, 384,
        Wh + O_Wg1, Wl + O_Wg1, 512, bg1, 512,
        nullptr, S1H + 1024, S1L + 1024, 1536, 128, 1, 1, 0, 0, 0, 0);
    cudaEventRecord(evB, sB);

    // main: L1a [W1|Ws1]
    gemm_tc3<128><<<dim3(8, 512), blk, SMEM128>>>(obsH, obsL, 384,
        Wh + O_W1s, Wl + O_W1s, 1024, bcat, 1024,
        nullptr, S1H, S1L, 1536, 256, 1, 1, 0, 0, 0, 0);

    // main waits Wg1, then z=3 batched layer-2 {W2,Ws2,Wg2}
    cudaStreamWaitEvent(0, evB, 0);
    gemm_tc3<128><<<dim3(2, 512, 3), blk, SMEM128>>>(S1H, S1L, 1536,
        Wh + O_W2, Wl + O_W2, 256, bcat + 1024, 256,
        nullptr, TTH, TTL, 256, 512, 1, 1,
        512, 131072, (size_t)BB * 256, 256);
    cudaEventRecord(evL2, 0);

    // sA: z=2 batched {Ws3,Wg3}: T2,T3 -> SG cols [0,128),[128,256)
    cudaStreamWaitEvent(sA, evL2, 0);
    gemm_tc3<128><<<dim3(1, 512, 2), blk, SMEM128, sA>>>(
        TTH + (size_t)BB * 256, TTL + (size_t)BB * 256, 256,
        Wh + O_Ws3, Wl + O_Ws3, 128, bcat + 1792, 128,
        SG, nullptr, nullptr, 256, 256, 0, 0,
        (size_t)BB * 256, 32768, 128, 128);
    cudaEventRecord(evA, sA);

    // main: Wp1 (T1 -> H), Wp2 (z=8)
    gemm_tc3<128><<<dim3(16, 512), blk, SMEM128>>>(TTH, TTL, 256,
        Wh + O_Wp1, Wl + O_Wp1, 2048, bp1, 2048,
        nullptr, HH, HL, 2048, 256, 1, 1, 0, 0, 0, 0);
    gemm_tc3<64><<<dim3(1, 512, 8), blk, SMEM64>>>(HH, HL, 2048,
        Wh + O_Wp2, Wl + O_Wp2, 64, bp2, 40,
        PS, nullptr, nullptr, 40, 256, 0, 0,
        256, 16384, (size_t)BB * 40, 40);

    // join, finalize
    cudaStreamWaitEvent(0, evA, 0);
    finalize_kernel<<<BB / 8, blk>>>(SG, PS, actions, Wgate, bgate, (float*)d_out);
}

// round 14
// speedup vs baseline: 1.5783x; 1.5783x over previous
#include <cuda_runtime.h>
#include <cuda_bf16.h>
#include <cstdint>

// ---------------------------------------------------------------------------
#define BB 65536
static constexpr float LRELU = 0.01f;
static constexpr float LOG_SQRT_2PI_C = 0.91893853320467274178f;

// ---------------------------------------------------------------------------
// Device scratch
// ---------------------------------------------------------------------------
__device__ uint16_t g_obsH[(size_t)BB * 384];
__device__ uint16_t g_obsL[(size_t)BB * 384];
__device__ uint16_t g_S1H[(size_t)BB * 1536];   // [W1|Ws1|Wg1] outputs
__device__ uint16_t g_S1L[(size_t)BB * 1536];
__device__ uint16_t g_TTH[(size_t)3 * BB * 256]; // T1|T2|T3 (z-batched out)
__device__ uint16_t g_TTL[(size_t)3 * BB * 256];
__device__ uint16_t g_HH[(size_t)BB * 2048];    // 8 heads concat on N
__device__ uint16_t g_HL[(size_t)BB * 2048];
__device__ float g_PS[(size_t)8 * BB * 40];
__device__ float g_SG[(size_t)BB * 256];
__device__ float g_bcat[2048];  // [0,1024)=b1|bs1  [1024,1792)=b2|bs2|bg2  [1792,2048)=bs3|bg3

static constexpr size_t WPOOL = 1441792;
__device__ uint16_t g_Wh[WPOOL];
__device__ uint16_t g_Wl[WPOOL];

// weight pool offsets (W2/Ws2/Wg2 adjacent; Ws3/Wg3 adjacent)
static constexpr size_t O_W1s = 0;         // 256 x 1024  ([W1|Ws1])
static constexpr size_t O_Wg1 = 262144;    // 128 x 512
static constexpr size_t O_W2  = 327680;    // 512 x 256  (x3, stride 131072)
static constexpr size_t O_Ws2 = 458752;
static constexpr size_t O_Wg2 = 589824;
static constexpr size_t O_Ws3 = 720896;    // 256 x 128  (x2, stride 32768)
static constexpr size_t O_Wg3 = 753664;
static constexpr size_t O_Wp1 = 786432;    // 256 x 2048 (heads on N)
static constexpr size_t O_Wp2 = 1310720;   // 8 x (256 x 64 pad)

// ---------------------------------------------------------------------------
// PTX helpers
// ---------------------------------------------------------------------------
__device__ __forceinline__ uint32_t smem_u32(const void* p) {
    uint32_t a;
    asm("{ .reg .u64 t; cvta.to.shared.u64 t, %1; cvt.u32.u64 %0, t; }"
        : "=r"(a) : "l"(p));
    return a;
}
__device__ __forceinline__ void cpa16(uint32_t dst, const void* src) {
    asm volatile("cp.async.cg.shared.global [%0], [%1], 16;"
                 :: "r"(dst), "l"(src) : "memory");
}
__device__ __forceinline__ void cp_commit() {
    asm volatile("cp.async.commit_group;" ::: "memory");
}
template <int N> __device__ __forceinline__ void cp_wait() {
    asm volatile("cp.async.wait_group %0;" :: "n"(N) : "memory");
}
__device__ __forceinline__ void ldsm4(uint32_t* r, uint32_t addr) {
    asm volatile("ldmatrix.sync.aligned.m8n8.x4.shared.b16 {%0,%1,%2,%3}, [%4];"
                 : "=r"(r[0]), "=r"(r[1]), "=r"(r[2]), "=r"(r[3]) : "r"(addr));
}
__device__ __forceinline__ void ldsm4t(uint32_t* r, uint32_t addr) {
    asm volatile("ldmatrix.sync.aligned.m8n8.x4.trans.shared.b16 {%0,%1,%2,%3}, [%4];"
                 : "=r"(r[0]), "=r"(r[1]), "=r"(r[2]), "=r"(r[3]) : "r"(addr));
}
__device__ __forceinline__ void mma_bf16(float* d, const uint32_t* a, const uint32_t* b) {
    asm volatile(
        "mma.sync.aligned.m16n8k16.row.col.f32.bf16.bf16.f32 "
        "{%0,%1,%2,%3}, {%4,%5,%6,%7}, {%8,%9}, {%0,%1,%2,%3};"
        : "+f"(d[0]), "+f"(d[1]), "+f"(d[2]), "+f"(d[3])
        : "r"(a[0]), "r"(a[1]), "r"(a[2]), "r"(a[3]), "r"(b[0]), "r"(b[1]));
}
__device__ __forceinline__ uint32_t pack_bf2(float a, float b) {
    __nv_bfloat162 h = __floats2bfloat162_rn(a, b);
    return *reinterpret_cast<uint32_t*>(&h);
}
__device__ __forceinline__ uint16_t bfh(float v) {
    __nv_bfloat16 h = __float2bfloat16_rn(v);
    return *reinterpret_cast<uint16_t*>(&h);
}
__device__ __forceinline__ float bff(uint16_t u) {
    __nv_bfloat16 h = *reinterpret_cast<__nv_bfloat16*>(&u);
    return __bfloat162float(h);
}

// ---------------------------------------------------------------------------
// Prep
// ---------------------------------------------------------------------------
struct WDesc { const float* src; int N, Np, ldn; size_t off; int tot; };
struct WPack { WDesc d[24]; int cnt; };

__global__ void prep_weights(WPack p) {
    for (int e = 0; e < p.cnt; e++) {
        const WDesc w = p.d[e];
        for (int i = blockIdx.x * blockDim.x + threadIdx.x; i < w.tot;
             i += gridDim.x * blockDim.x) {
            int k = i / w.Np, n = i % w.Np;
            float v = (n < w.N) ? w.src[(size_t)k * w.N + n] : 0.f;
            uint16_t h = bfh(v);
            size_t dst = w.off + (size_t)k * w.ldn + n;
            g_Wh[dst] = h;
            g_Wl[dst] = bfh(v - bff(h));
        }
    }
}

__global__ void prep_obs(const float* __restrict__ src, size_t n4) {
    size_t i = (size_t)blockIdx.x * blockDim.x + threadIdx.x;
    if (i >= n4) return;
    float4 v = ((const float4*)src)[i];
    float h0 = bff(bfh(v.x)), h1 = bff(bfh(v.y));
    float h2 = bff(bfh(v.z)), h3 = bff(bfh(v.w));
    uint32_t* dh = (uint32_t*)&g_obsH[i * 4];
    uint32_t* dl = (uint32_t*)&g_obsL[i * 4];
    dh[0] = pack_bf2(h0, h1); dh[1] = pack_bf2(h2, h3);
    dl[0] = pack_bf2(v.x - h0, v.y - h1); dl[1] = pack_bf2(v.z - h2, v.w - h3);
}

__global__ void prep_bias(const float* __restrict__ b1, const float* __restrict__ bs1,
                          const float* __restrict__ b2, const float* __restrict__ bs2,
                          const float* __restrict__ bg2,
                          const float* __restrict__ bs3, const float* __restrict__ bg3) {
    int i = blockIdx.x * blockDim.x + threadIdx.x;
    if (i < 512)       g_bcat[i] = b1[i];
    else if (i < 1024) g_bcat[i] = bs1[i - 512];
    else if (i < 1280) g_bcat[i] = b2[i - 1024];
    else if (i < 1536) g_bcat[i] = bs2[i - 1280];
    else if (i < 1792) g_bcat[i] = bg2[i - 1536];
    else if (i < 1920) g_bcat[i] = bs3[i - 1792];
    else if (i < 2048) g_bcat[i] = bg3[i - 1920];
}

// ---------------------------------------------------------------------------
// Split-bf16 GEMM, CTA tile 128 x NT, warp tile 32 x NT/2, K-chunk 32,
// 2-stage cp.async ring (R9-proven loop), 2 CTAs/SM.
// ---------------------------------------------------------------------------
template <int NT>
__global__ void __launch_bounds__(256, 2) gemm_tc3(
    const uint16_t* __restrict__ Ah, const uint16_t* __restrict__ Al, int lda,
    const uint16_t* __restrict__ Bh, const uint16_t* __restrict__ Bl, int ldb,
    const float* __restrict__ bias, int Nreal,
    float* __restrict__ Cf, uint16_t* __restrict__ Chi, uint16_t* __restrict__ Clo,
    int ldc, int K, int act, int mode,
    size_t strideAz, size_t strideBz, size_t strideCz, int biasStride)
{
    constexpr int WN   = NT / 2;
    constexpr int NI   = WN / 8;
    constexpr int BST  = NT + 8;
    constexpr int SM_AL = 10240;
    constexpr int SM_BH = 20480;
    constexpr int SM_BL = 20480 + 32 * BST * 2;
    constexpr int STAGE = 20480 + 2 * 32 * BST * 2;

    extern __shared__ __align__(16) char smem[];
    const uint32_t sb = smem_u32(smem);

    const int t    = threadIdx.x;
    const int lane = t & 31;
    const int wid  = t >> 5;
    const int wm   = wid & 3;
    const int wn   = wid >> 2;
    const int m0   = blockIdx.y * 128;
    const int n0   = blockIdx.x * NT;
    const int z    = blockIdx.z;

    const uint16_t* Abase_h = Ah + (size_t)z * strideAz;
    const uint16_t* Abase_l = Al + (size_t)z * strideAz;
    const uint16_t* Bbase_h = Bh + (size_t)z * strideBz;
    const uint16_t* Bbase_l = Bl + (size_t)z * strideBz;
    const float*    biasp   = bias + (size_t)z * biasStride;

    auto issue = [&](int c, int buf) {
        const uint32_t base = sb + buf * STAGE;
        const int k0 = c << 5;
#pragma unroll
        for (int j = 0; j < 2; j++) {
            int i = t + 256 * j;
            int ar = i >> 2, as = i & 3;
            uint32_t off = (ar * 40 + as * 8) * 2;
            const uint16_t* sh = Abase_h + (size_t)(m0 + ar) * lda + k0 + as * 8;
            const uint16_t* sl = Abase_l + (size_t)(m0 + ar) * lda + k0 + as * 8;
            cpa16(base + off, sh);
            cpa16(base + SM_AL + off, sl);
        }
#pragma unroll
        for (int j = 0; j < NT / 64; j++) {
            int i = t + 256 * j;
            int br = i / (NT / 8), bs = i % (NT / 8);
            uint32_t off = (br * BST + bs * 8) * 2;
            const uint16_t* sh = Bbase_h + (size_t)(k0 + br) * ldb + n0 + bs * 8;
            const uint16_t* sl = Bbase_l + (size_t)(k0 + br) * ldb + n0 + bs * 8;
            cpa16(base + SM_BH + off, sh);
            cpa16(base + SM_BL + off, sl);
        }
    };

    float acc[2][NI][4];
#pragma unroll
    for (int i = 0; i < 2; i++)
#pragma unroll
        for (int j = 0; j < NI; j++)
#pragma unroll
            for (int q = 0; q < 4; q++) acc[i][j][q] = 0.f;

    const int nch = K >> 5;
    issue(0, 0);
    cp_commit();

    for (int c = 0; c < nch; c++) {
        if (c + 1 < nch) {
            issue(c + 1, (c + 1) & 1);
            cp_commit();
            cp_wait<1>();
        } else {
            cp_wait<0>();
        }
        __syncthreads();

        const uint32_t base = sb + (c & 1) * STAGE;
#pragma unroll
        for (int ks = 0; ks < 32; ks += 16) {
            uint32_t Afh[2][4], Afl[2][4], Bfh[NI][2], Bfl[NI][2];
            {
                int r  = lane & 15;
                int kq = (lane >> 4) * 8;
#pragma unroll
                for (int mi = 0; mi < 2; mi++) {
                    int m = wm * 32 + mi * 16 + r;
                    uint32_t off = (m * 40 + ks + kq) * 2;
                    ldsm4(Afh[mi], base + off);
                    ldsm4(Afl[mi], base + SM_AL + off);
                }
            }
            {
                int g  = lane >> 3;
                int rr = lane & 7;
                int krow = ks + (g & 1) * 8 + rr;
                int ncol = (g >> 1) * 8;
#pragma unroll
                for (int blk = 0; blk < NI / 2; blk++) {
                    int nb = wn * WN + blk * 16 + ncol;
                    uint32_t off = (krow * BST + nb) * 2;
                    ldsm4t(&Bfh[blk * 2][0], base + SM_BH + off);
                    ldsm4t(&Bfl[blk * 2][0], base + SM_BL + off);
                }
            }
#pragma unroll
            for (int mi = 0; mi < 2; mi++)
#pragma unroll
                for (int ni = 0; ni < NI; ni++) {
                    mma_bf16(acc[mi][ni], Afh[mi], Bfh[ni]);
                    mma_bf16(acc[mi][ni], Afh[mi], Bfl[ni]);
                    mma_bf16(acc[mi][ni], Afl[mi], Bfh[ni]);
                }
        }
        __syncthreads();
    }

    // ---- epilogue ----
    const int r4 = lane >> 2;
    const int c2 = (lane & 3) * 2;
#pragma unroll
    for (int mi = 0; mi < 2; mi++) {
#pragma unroll
        for (int ni = 0; ni < NI; ni++) {
            int col = n0 + wn * WN + ni * 8 + c2;
            int row = m0 + wm * 32 + mi * 16 + r4;
            if (mode == 0 && col >= Nreal) continue;
            float b0 = biasp[col], b1 = biasp[col + 1];
            float v0 = acc[mi][ni][0] + b0;
            float v1 = acc[mi][ni][1] + b1;
            float v2 = acc[mi][ni][2] + b0;
            float v3 = acc[mi][ni][3] + b1;
            if (act) {
                v0 = v0 > 0.f ? v0 : LRELU * v0;
                v1 = v1 > 0.f ? v1 : LRELU * v1;
                v2 = v2 > 0.f ? v2 : LRELU * v2;
                v3 = v3 > 0.f ? v3 : LRELU * v3;
            }
            size_t i0 = (size_t)z * strideCz + (size_t)row * ldc + col;
            size_t i1 = (size_t)z * strideCz + (size_t)(row + 8) * ldc + col;
            if (mode == 0) {
                *(float2*)&Cf[i0] = make_float2(v0, v1);
                *(float2*)&Cf[i1] = make_float2(v2, v3);
            } else {
                float h0 = bff(bfh(v0)), h1 = bff(bfh(v1));
                float h2 = bff(bfh(v2)), h3 = bff(bfh(v3));
                *(uint32_t*)&Chi[i0] = pack_bf2(h0, h1);
                *(uint32_t*)&Clo[i0] = pack_bf2(v0 - h0, v1 - h1);
                *(uint32_t*)&Chi[i1] = pack_bf2(h2, h3);
                *(uint32_t*)&Clo[i1] = pack_bf2(v2 - h2, v3 - h3);
            }
        }
    }
}

// ---------------------------------------------------------------------------
// Finalize
// ---------------------------------------------------------------------------
__global__ __launch_bounds__(256) void finalize_kernel(
    const float* __restrict__ SG, const float* __restrict__ PS,
    const float* __restrict__ actions,
    const float* __restrict__ Wgate, const float* __restrict__ bgate,
    float* __restrict__ out)
{
    __shared__ float Wg_s[8 * 256];
    const int t = threadIdx.x;
    for (int i = t; i < 2048; i += 256) {
        int k = i >> 3, p = i & 7;
        Wg_s[p * 256 + k] = Wgate[i];
    }
    __syncthreads();

    const int warp = t >> 5, lane = t & 31;
    const size_t row = (size_t)blockIdx.x * 8 + warp;

    float accp[8] = {0, 0, 0, 0, 0, 0, 0, 0};
#pragma unroll
    for (int i = 0; i < 8; i++) {
        float v = SG[row * 256 + lane + 32 * i];
        v = v > 0.f ? v : LRELU * v;
#pragma unroll
        for (int p = 0; p < 8; p++)
            accp[p] += v * Wg_s[p * 256 + lane + 32 * i];
    }
#pragma unroll
    for (int off = 16; off; off >>= 1)
#pragma unroll
        for (int p = 0; p < 8; p++)
            accp[p] += __shfl_xor_sync(0xffffffffu, accp[p], off);

    float wg[8];
#pragma unroll
    for (int p = 0; p < 8; p++)
        wg[p] = expf(accp[p] + bgate[p]);

    float lp = 0.f, ent = 0.f;
    if (lane < 20) {
        float s1 = 0.f, s2 = 0.f;
#pragma unroll
        for (int p = 0; p < 8; p++) {
            const float* psr = PS + ((size_t)p * BB + row) * 40;
            float mu = psr[lane];
            float lg = psr[20 + lane];
            float inv = wg[p] * expf(-lg);
            s1 += mu * inv;
            s2 += inv;
        }
        float a = actions[row * 20 + lane];
        float z = (a - s1 / s2) * s2;
        float logsig = -logf(s2);
        lp  = -0.5f * z * z - logsig - LOG_SQRT_2PI_C;
        ent = 0.5f + LOG_SQRT_2PI_C + logsig;
    }
#pragma unroll
    for (int off = 16; off; off >>= 1) {
        lp  += __shfl_xor_sync(0xffffffffu, lp,  off);
        ent += __shfl_xor_sync(0xffffffffu, ent, off);
    }
    if (lane == 0) {
        out[row * 2]     = lp;
        out[row * 2 + 1] = ent;
    }
}

// ---------------------------------------------------------------------------
// Launcher
// ---------------------------------------------------------------------------
static constexpr int SMEM128 = 2 * (20480 + 2 * 32 * 136 * 2);  // 75776
static constexpr int SMEM64  = 2 * (20480 + 2 * 32 * 72 * 2);   // 59392

extern "C" void kernel_launch(void* const* d_in, const int* in_sizes, int n_in,
                              void* d_out, int out_size)
{
    const float* obs     = (const float*)d_in[0];
    const float* actions = (const float*)d_in[1];
    const float* W1      = (const float*)d_in[2];
    const float* b1      = (const float*)d_in[3];
    const float* W2      = (const float*)d_in[4];
    const float* b2      = (const float*)d_in[5];
    const float* Wp1     = (const float*)d_in[6];
    const float* bp1     = (const float*)d_in[7];
    const float* Wp2     = (const float*)d_in[8];
    const float* bp2     = (const float*)d_in[9];
    const float* Ws1     = (const float*)d_in[10];
    const float* bs1     = (const float*)d_in[11];
    const float* Ws2     = (const float*)d_in[12];
    const float* bs2     = (const float*)d_in[13];
    const float* Ws3     = (const float*)d_in[14];
    const float* bs3     = (const float*)d_in[15];
    const float* Wg1     = (const float*)d_in[16];
    const float* bg1     = (const float*)d_in[17];
    const float* Wg2     = (const float*)d_in[18];
    const float* bg2     = (const float*)d_in[19];
    const float* Wg3     = (const float*)d_in[20];
    const float* bg3     = (const float*)d_in[21];
    const float* Wgate   = (const float*)d_in[22];
    const float* bgate   = (const float*)d_in[23];

    uint16_t *obsH, *obsL, *S1H, *S1L, *TTH, *TTL, *HH, *HL, *Wh, *Wl;
    float *PS, *SG, *bcat;
    cudaGetSymbolAddress((void**)&obsH, g_obsH);
    cudaGetSymbolAddress((void**)&obsL, g_obsL);
    cudaGetSymbolAddress((void**)&S1H, g_S1H);
    cudaGetSymbolAddress((void**)&S1L, g_S1L);
    cudaGetSymbolAddress((void**)&TTH, g_TTH);
    cudaGetSymbolAddress((void**)&TTL, g_TTL);
    cudaGetSymbolAddress((void**)&HH, g_HH);
    cudaGetSymbolAddress((void**)&HL, g_HL);
    cudaGetSymbolAddress((void**)&Wh, g_Wh);
    cudaGetSymbolAddress((void**)&Wl, g_Wl);
    cudaGetSymbolAddress((void**)&PS, g_PS);
    cudaGetSymbolAddress((void**)&SG, g_SG);
    cudaGetSymbolAddress((void**)&bcat, g_bcat);

    cudaFuncSetAttribute(gemm_tc3<128>, cudaFuncAttributeMaxDynamicSharedMemorySize, SMEM128);
    cudaFuncSetAttribute(gemm_tc3<64>,  cudaFuncAttributeMaxDynamicSharedMemorySize, SMEM64);

    static cudaStream_t sA = nullptr, sB = nullptr;
    static cudaEvent_t evRoot = nullptr, evL2 = nullptr, evA = nullptr, evB = nullptr;
    if (sA == nullptr) {
        cudaStreamCreateWithFlags(&sA, cudaStreamNonBlocking);
        cudaStreamCreateWithFlags(&sB, cudaStreamNonBlocking);
        cudaEventCreateWithFlags(&evRoot, cudaEventDisableTiming);
        cudaEventCreateWithFlags(&evL2, cudaEventDisableTiming);
        cudaEventCreateWithFlags(&evA, cudaEventDisableTiming);
        cudaEventCreateWithFlags(&evB, cudaEventDisableTiming);
    }

    // ---- prep ----
    WPack wp{};
    int e = 0;
    wp.d[e++] = {W1,  512, 512, 1024, O_W1s,       256 * 512};
    wp.d[e++] = {Ws1, 512, 512, 1024, O_W1s + 512, 256 * 512};
    wp.d[e++] = {Wg1, 512, 512, 512,  O_Wg1, 128 * 512};
    wp.d[e++] = {W2,  256, 256, 256,  O_W2,  512 * 256};
    wp.d[e++] = {Ws2, 256, 256, 256,  O_Ws2, 512 * 256};
    wp.d[e++] = {Wg2, 256, 256, 256,  O_Wg2, 512 * 256};
    wp.d[e++] = {Ws3, 128, 128, 128,  O_Ws3, 256 * 128};
    wp.d[e++] = {Wg3, 128, 128, 128,  O_Wg3, 256 * 128};
    for (int p = 0; p < 8; p++)
        wp.d[e++] = {Wp1 + (size_t)p * 65536, 256, 256, 2048,
                     O_Wp1 + (size_t)p * 256, 256 * 256};
    for (int p = 0; p < 8; p++)
        wp.d[e++] = {Wp2 + (size_t)p * 10240, 40, 64, 64,
                     O_Wp2 + (size_t)p * 16384, 256 * 64};
    wp.cnt = e;
    prep_weights<<<512, 256>>>(wp);
    size_t n4 = (size_t)BB * 384 / 4;
    prep_obs<<<(unsigned)((n4 + 255) / 256), 256>>>(obs, n4);
    prep_bias<<<8, 256>>>(b1, bs1, b2, bs2, bg2, bs3, bg3);

    dim3 blk(256);

    // fork
    cudaEventRecord(evRoot, 0);
    cudaStreamWaitEvent(sB, evRoot, 0);

    // sB: Wg1 (independent; reads obs goal cols)
    gemm_tc3<128><<<dim3(4, 512), blk, SMEM128, sB>>>(obsH + 256, obsL + 256, 384,
        Wh + O_Wg1, Wl + O_Wg1, 512, bg1, 512,
        nullptr, S1H + 1024, S1L + 1024, 1536, 128, 1, 1, 0, 0, 0, 0);
    cudaEventRecord(evB, sB);

    // main: L1a [W1|Ws1]
    gemm_tc3<128><<<dim3(8, 512), blk, SMEM128>>>(obsH, obsL, 384,
        Wh + O_W1s, Wl + O_W1s, 1024, bcat, 1024,
        nullptr, S1H, S1L, 1536, 256, 1, 1, 0, 0, 0, 0);

    // main waits Wg1, then z=3 batched layer-2 {W2,Ws2,Wg2}
    cudaStreamWaitEvent(0, evB, 0);
    gemm_tc3<128><<<dim3(2, 512, 3), blk, SMEM128>>>(S1H, S1L, 1536,
        Wh + O_W2, Wl + O_W2, 256, bcat + 1024, 256,
        nullptr, TTH, TTL, 256, 512, 1, 1,
        512, 131072, (size_t)BB * 256, 256);
    cudaEventRecord(evL2, 0);

    // sA: z=2 batched {Ws3,Wg3}: T2,T3 -> SG cols [0,128),[128,256)
    cudaStreamWaitEvent(sA, evL2, 0);
    gemm_tc3<128><<<dim3(1, 512, 2), blk, SMEM128, sA>>>(
        TTH + (size_t)BB * 256, TTL + (size_t)BB * 256, 256,
        Wh + O_Ws3, Wl + O_Ws3, 128, bcat + 1792, 128,
        SG, nullptr, nullptr, 256, 256, 0, 0,
        (size_t)BB * 256, 32768, 128, 128);
    cudaEventRecord(evA, sA);

    // main: Wp1 (T1 -> H), Wp2 (z=8)
    gemm_tc3<128><<<dim3(16, 512), blk, SMEM128>>>(TTH, TTL, 256,
        Wh + O_Wp1, Wl + O_Wp1, 2048, bp1, 2048,
        nullptr, HH, HL, 2048, 256, 1, 1, 0, 0, 0, 0);
    gemm_tc3<64><<<dim3(1, 512, 8), blk, SMEM64>>>(HH, HL, 2048,
        Wh + O_Wp2, Wl + O_Wp2, 64, bp2, 40,
        PS, nullptr, nullptr, 40, 256, 0, 0,
        256, 16384, (size_t)BB * 40, 40);

    // join, finalize
    cudaStreamWaitEvent(0, evA, 0);
    finalize_kernel<<<BB / 8, blk>>>(SG, PS, actions, Wgate, bgate, (float*)d_out);
}